// round 15
// baseline (speedup 1.0000x reference)
#include <cuda_runtime.h>
#include <cstdint>

#define BATCH 64
#define HH 512
#define WW 512
#define TILE_H 128
#define NROWT (HH / TILE_H)            // 4
#define NSTRIP 8                       // 64-col warp strips
#define NPART (BATCH * NROWT * NSTRIP) // 2048
#define DEPTH 8
#define DIST 6
#define NSTEP (TILE_H + 10)            // 138 staged rows per tile

typedef unsigned long long u64;

__device__ float g_partials[NPART];
__device__ unsigned int g_ticket = 0;

// ---- packed f32x2 helpers (Blackwell FFMA2 path, PTX-only) ----
__device__ __forceinline__ u64 pk2(float lo, float hi) {
    u64 r; asm("mov.b64 %0, {%1, %2};" : "=l"(r) : "f"(lo), "f"(hi)); return r;
}
__device__ __forceinline__ void upk2(u64 v, float& lo, float& hi) {
    asm("mov.b64 {%0, %1}, %2;" : "=f"(lo), "=f"(hi) : "l"(v));
}
__device__ __forceinline__ u64 f2mul(u64 a, u64 b) {
    u64 d; asm("mul.rn.f32x2 %0, %1, %2;" : "=l"(d) : "l"(a), "l"(b)); return d;
}
__device__ __forceinline__ u64 f2add(u64 a, u64 b) {
    u64 d; asm("add.rn.f32x2 %0, %1, %2;" : "=l"(d) : "l"(a), "l"(b)); return d;
}
__device__ __forceinline__ u64 f2fma(u64 a, u64 b, u64 c) {
    u64 d; asm("fma.rn.f32x2 %0, %1, %2, %3;" : "=l"(d) : "l"(a), "l"(b), "l"(c)); return d;
}

__global__ __launch_bounds__(32, 16)
void ssim_map_kernel(const float* __restrict__ x, const float* __restrict__ y,
                     const float* __restrict__ win, float* __restrict__ out)
{
    // warp-private staging ring: [slot][field][8 halo + 64 + 8 halo]  (5120 B)
    // 16B alignment REQUIRED for cp.async 16B destinations.
    __shared__ __align__(16) float sbuf[DEPTH][2][80];

    const int t     = threadIdx.x;          // 0..31
    const int strip = blockIdx.x & 7;
    const int rt    = blockIdx.x >> 3;
    const int b     = blockIdx.y;
    const int cw    = strip * 64;           // first output column of this warp
    const int r0    = rt * TILE_H;
    const float* xb = x + (size_t)b * HH * WW;
    const float* yb = y + (size_t)b * HH * WW;

    const bool lvalid = (cw > 0);
    const bool rvalid = (cw + 64 < WW);

    // zero ONLY invalid-side halos once (never written again)
    if (t < DEPTH) {
        float4 z = make_float4(0.f, 0.f, 0.f, 0.f);
        #pragma unroll
        for (int f = 0; f < 2; ++f) {
            if (!lvalid) { *(float4*)&sbuf[t][f][0]  = z; *(float4*)&sbuf[t][f][4]  = z; }
            if (!rvalid) { *(float4*)&sbuf[t][f][72] = z; *(float4*)&sbuf[t][f][76] = z; }
        }
    }

    // 1D taps g[i] = sum_j w2d[i][j] (sum g == 1), packed (g,g)
    u64 g2[11];
    #pragma unroll
    for (int i = 0; i < 11; ++i) {
        float s = 0.f;
        #pragma unroll
        for (int j = 0; j < 11; ++j) s += win[i * 11 + j];
        g2[i] = pk2(s, s);
    }

    const u64 HC1  = pk2(5e-5f, 5e-5f);     // C1/2
    const u64 HC2  = pk2(4.5e-4f, 4.5e-4f); // C2/2
    const u64 FC1  = pk2(1e-4f, 1e-4f);     // C1
    const u64 FC2  = pk2(9e-4f, 9e-4f);     // C2
    const u64 NEG1 = pk2(-1.f, -1.f);

    // lane roles for fills (computed once)
    const int  l16    = t & 15;
    const int  hf     = (t >> 2) & 1;        // halo field: 0=x, 1=y
    const int  hs     = (t >> 1) & 1;        // halo side: 0=left, 1=right
    const int  hk     = t & 1;               // halo chunk within side
    const bool hv     = (t < 8) && (hs ? rvalid : lvalid);
    const int  hdoff  = (hs ? 72 : 0) + hk * 4;
    const int  hcol   = hs ? (cw + 64 + hk * 4) : (cw - 8 + hk * 4);
    const float* mplane = (t < 16) ? xb : yb;
    const float* hplane = hf ? yb : xb;

    // running fill state (sequential rows): advance pointers by WW per fill
    int          fr   = r0 - 5;                                    // next row to fill
    int          fs   = 0;                                         // next ring slot
    const float* msrc = mplane + (size_t)(r0 - 5) * WW + cw + l16 * 4;
    const float* hsrc = hplane + (size_t)(r0 - 5) * WW + hcol;

    // ---- row fill (sequential): 16B cp.async; zeros for out-of-image rows ----
    auto fill_row = [&]() {
        float* bx = sbuf[fs][0];
        float* by = sbuf[fs][1];
        float* mdst = ((t < 16) ? bx : by) + 8 + l16 * 4;
        float* hdst = (hf ? by : bx) + hdoff;
        if ((unsigned)fr < (unsigned)HH) {
            unsigned d = (unsigned)__cvta_generic_to_shared(mdst);
            asm volatile("cp.async.cg.shared.global [%0], [%1], 16;" :: "r"(d), "l"(msrc) : "memory");
            if (hv) {
                unsigned dh = (unsigned)__cvta_generic_to_shared(hdst);
                asm volatile("cp.async.cg.shared.global [%0], [%1], 16;" :: "r"(dh), "l"(hsrc) : "memory");
            }
        } else {
            float4 z = make_float4(0.f, 0.f, 0.f, 0.f);
            *(float4*)mdst = z;
            if (hv) *(float4*)hdst = z;
        }
        ++fr;
        if (++fs == DEPTH) fs = 0;
        msrc += WW;
        hsrc += WW;
    };

    // prologue: prefetch rows 0..DIST-1, one commit group each
    #pragma unroll
    for (int p = 0; p < DIST; ++p) {
        fill_row();
        asm volatile("cp.async.commit_group;" ::: "memory");
    }

    // register ring: 11 rows x 4 packed fields (mu_x, mu_y, x^2+y^2, x*y)
    u64 RX[11], RY[11], RS[11], RP[11];
    float acc = 0.f;

    for (int blk = 0; blk < 13; ++blk) {
        #pragma unroll
        for (int ph = 0; ph < 11; ++ph) {
            const int pr = blk * 11 + ph;
            if (pr < NSTEP) {
                // warp-private pipeline: slot (pr+6)&7 = (pr-2)&7 was consumed
                // by this warp two iterations ago -> no block barrier needed.
                if (pr + DIST < NSTEP) fill_row();
                asm volatile("cp.async.commit_group;" ::: "memory");
                asm volatile("cp.async.wait_group %0;" :: "n"(DIST) : "memory");
                __syncwarp();   // make warp-mates' staged row visible

                // stage 7 aligned u64 pairs per field: XA[i] = (xr[2i], xr[2i+1])
                const u64* xv = (const u64*)sbuf[pr & 7][0] + (t + 1);
                const u64* yv = (const u64*)sbuf[pr & 7][1] + (t + 1);
                u64 XA[7], YA[7];
                #pragma unroll
                for (int i = 0; i < 7; ++i) { XA[i] = xv[i]; YA[i] = yv[i]; }
                // scalar views (register aliases, no instructions)
                float xl[7], xh[7], yl[7], yh[7];
                #pragma unroll
                for (int i = 0; i < 7; ++i) {
                    upk2(XA[i], xl[i], xh[i]);
                    upk2(YA[i], yl[i], yh[i]);
                }

                // horizontal 11-tap conv over column pair (cw+2t, cw+2t+1):
                // tap j operand = (xr[1+j], xr[2+j]);
                //  odd  j=2m+1 -> aligned  XA[m+1]          (direct, no MOV)
                //  even j=2m   -> unaligned (xh[m], xl[m+1]) (pk2)
                u64 hx = 0, hy = 0, hsum = 0, hp = 0;
                #pragma unroll
                for (int m = 0; m < 6; ++m) {          // even taps j = 2m
                    u64 ax = pk2(xh[m], xl[m + 1]);
                    u64 ay = pk2(yh[m], yl[m + 1]);
                    hx = f2fma(g2[2 * m], ax, hx);
                    hy = f2fma(g2[2 * m], ay, hy);
                    u64 ss = f2mul(ax, ax);
                    ss = f2fma(ay, ay, ss);
                    hsum = f2fma(g2[2 * m], ss, hsum);
                    hp = f2fma(g2[2 * m], f2mul(ax, ay), hp);
                }
                #pragma unroll
                for (int m = 0; m < 5; ++m) {          // odd taps j = 2m+1
                    u64 ax = XA[m + 1];
                    u64 ay = YA[m + 1];
                    hx = f2fma(g2[2 * m + 1], ax, hx);
                    hy = f2fma(g2[2 * m + 1], ay, hy);
                    u64 ss = f2mul(ax, ax);
                    ss = f2fma(ay, ay, ss);
                    hsum = f2fma(g2[2 * m + 1], ss, hsum);
                    hp = f2fma(g2[2 * m + 1], f2mul(ax, ay), hp);
                }
                RX[ph] = hx; RY[ph] = hy; RS[ph] = hsum; RP[ph] = hp;

                // vertical 11-tap conv + SSIM once ring is warm
                if (pr >= 10) {
                    u64 mx = f2mul(g2[0], RX[(ph + 1) % 11]);
                    u64 my = f2mul(g2[0], RY[(ph + 1) % 11]);
                    u64 sp = f2mul(g2[0], RS[(ph + 1) % 11]);
                    u64 sx = f2mul(g2[0], RP[(ph + 1) % 11]);
                    #pragma unroll
                    for (int k = 1; k < 11; ++k) {
                        const int sl = (ph + 1 + k) % 11;
                        mx = f2fma(g2[k], RX[sl], mx);
                        my = f2fma(g2[k], RY[sl], my);
                        sp = f2fma(g2[k], RS[sl], sp);
                        sx = f2fma(g2[k], RP[sl], sx);
                    }
                    u64 mx2 = f2mul(mx, mx);
                    u64 my2 = f2mul(my, my);
                    u64 mxy = f2mul(mx, my);
                    u64 msq = f2add(mx2, my2);
                    u64 vp  = f2fma(msq, NEG1, sp);    // sigma_x^2 + sigma_y^2
                    u64 vxy = f2fma(mxy, NEG1, sx);    // sigma_xy
                    u64 t1  = f2add(mxy, HC1);
                    u64 t2  = f2add(vxy, HC2);
                    u64 num = f2mul(t1, t2);           // ssim = 4*num/den
                    u64 t3  = f2add(msq, FC1);
                    u64 t4  = f2add(vp,  FC2);
                    u64 den = f2mul(t3, t4);
                    float n0, n1, d0, d1;
                    upk2(num, n0, n1);
                    upk2(den, d0, d1);
                    // one division for both lanes: (n0*d1 + n1*d0)/(d0*d1)
                    acc += __fdividef(fmaf(n0, d1, n1 * d0), d0 * d1);
                }
            }
        }
    }

    // ---- deterministic warp reduction -> partial ----
    #pragma unroll
    for (int o = 16; o; o >>= 1) acc += __shfl_down_sync(0xFFFFFFFFu, acc, o);

    int last = 0;
    if (t == 0) {
        g_partials[blockIdx.y * (NROWT * NSTRIP) + blockIdx.x] = acc;
        __threadfence();
        unsigned old = atomicAdd(&g_ticket, 1u);
        last = (old == NPART - 1);
    }
    last = __shfl_sync(0xFFFFFFFFu, last, 0);

    // ---- last warp: fixed-order final reduction (deterministic) ----
    if (last) {
        __threadfence();
        float v = 0.f;
        #pragma unroll
        for (int k = 0; k < NPART / 32; ++k)
            v += g_partials[t + 32 * k];
        #pragma unroll
        for (int o = 16; o; o >>= 1) v += __shfl_down_sync(0xFFFFFFFFu, v, o);
        if (t == 0) {
            // accumulated terms were num/4 / den -> scale by 4 / (B*H*W)
            out[0] = v * (4.0f / 16777216.0f);
            g_ticket = 0;   // reset for next graph replay
        }
    }
}

extern "C" void kernel_launch(void* const* d_in, const int* in_sizes, int n_in,
                              void* d_out, int out_size)
{
    const float* x   = (const float*)d_in[0];
    const float* y   = (const float*)d_in[1];
    const float* win = (const float*)d_in[2];
    float* out = (float*)d_out;

    dim3 grid(NROWT * NSTRIP, BATCH);   // (32, 64) = 2048 one-warp CTAs, single wave
    ssim_map_kernel<<<grid, 32>>>(x, y, win, out);
}

// round 16
// speedup vs baseline: 1.1148x; 1.1148x over previous
#include <cuda_runtime.h>
#include <cstdint>

#define BATCH 64
#define HH 512
#define WW 512
#define TILE_H 64
#define NROWT (HH / TILE_H)            // 8
#define NSTRIP 8                       // 64-col warp strips
#define NPART (BATCH * NROWT * NSTRIP) // 4096
#define DEPTH 8
#define DIST 6
#define NSTEP (TILE_H + 10)            // 74 staged rows per tile

typedef unsigned long long u64;

__device__ float g_partials[NPART];
__device__ unsigned int g_ticket = 0;

// ---- packed f32x2 helpers (Blackwell FFMA2 path, PTX-only) ----
__device__ __forceinline__ u64 pk2(float lo, float hi) {
    u64 r; asm("mov.b64 %0, {%1, %2};" : "=l"(r) : "f"(lo), "f"(hi)); return r;
}
__device__ __forceinline__ void upk2(u64 v, float& lo, float& hi) {
    asm("mov.b64 {%0, %1}, %2;" : "=f"(lo), "=f"(hi) : "l"(v));
}
__device__ __forceinline__ u64 f2mul(u64 a, u64 b) {
    u64 d; asm("mul.rn.f32x2 %0, %1, %2;" : "=l"(d) : "l"(a), "l"(b)); return d;
}
__device__ __forceinline__ u64 f2add(u64 a, u64 b) {
    u64 d; asm("add.rn.f32x2 %0, %1, %2;" : "=l"(d) : "l"(a), "l"(b)); return d;
}
__device__ __forceinline__ u64 f2fma(u64 a, u64 b, u64 c) {
    u64 d; asm("fma.rn.f32x2 %0, %1, %2, %3;" : "=l"(d) : "l"(a), "l"(b), "l"(c)); return d;
}

__global__ __launch_bounds__(32, 16)
void ssim_map_kernel(const float* __restrict__ x, const float* __restrict__ y,
                     const float* __restrict__ win, float* __restrict__ out)
{
    // warp-private staging ring: [slot][field][8 halo + 64 + 8 halo]  (5120 B)
    // 16B alignment REQUIRED for cp.async 16B destinations.
    __shared__ __align__(16) float sbuf[DEPTH][2][80];

    const int t     = threadIdx.x;          // 0..31
    const int strip = blockIdx.x & 7;
    const int rt    = blockIdx.x >> 3;
    const int b     = blockIdx.y;
    const int cw    = strip * 64;           // first output column of this warp
    const int r0    = rt * TILE_H;
    const float* xb = x + (size_t)b * HH * WW;
    const float* yb = y + (size_t)b * HH * WW;

    const bool lvalid = (cw > 0);
    const bool rvalid = (cw + 64 < WW);

    // zero ONLY invalid-side halos once (never written again)
    if (t < DEPTH) {
        float4 z = make_float4(0.f, 0.f, 0.f, 0.f);
        #pragma unroll
        for (int f = 0; f < 2; ++f) {
            if (!lvalid) { *(float4*)&sbuf[t][f][0]  = z; *(float4*)&sbuf[t][f][4]  = z; }
            if (!rvalid) { *(float4*)&sbuf[t][f][72] = z; *(float4*)&sbuf[t][f][76] = z; }
        }
    }

    // 1D taps g[i] = sum_j w2d[i][j] (sum g == 1), packed (g,g)
    u64 g2[11];
    #pragma unroll
    for (int i = 0; i < 11; ++i) {
        float s = 0.f;
        #pragma unroll
        for (int j = 0; j < 11; ++j) s += win[i * 11 + j];
        g2[i] = pk2(s, s);
    }

    const u64 HC1  = pk2(5e-5f, 5e-5f);     // C1/2
    const u64 HC2  = pk2(4.5e-4f, 4.5e-4f); // C2/2
    const u64 FC1  = pk2(1e-4f, 1e-4f);     // C1
    const u64 FC2  = pk2(9e-4f, 9e-4f);     // C2
    const u64 NEG1 = pk2(-1.f, -1.f);

    // lane roles for fills (computed once)
    const int  l16    = t & 15;
    const int  hf     = (t >> 2) & 1;        // halo field: 0=x, 1=y
    const int  hs     = (t >> 1) & 1;        // halo side: 0=left, 1=right
    const int  hk     = t & 1;               // halo chunk within side
    const bool hv     = (t < 8) && (hs ? rvalid : lvalid);
    const int  hdoff  = (hs ? 72 : 0) + hk * 4;
    const int  hcol   = hs ? (cw + 64 + hk * 4) : (cw - 8 + hk * 4);
    const float* mplane = (t < 16) ? xb : yb;
    const float* hplane = hf ? yb : xb;

    // running fill state (sequential rows): advance pointers by WW per fill
    int          fr   = r0 - 5;                                    // next row to fill
    int          fs   = 0;                                         // next ring slot
    const float* msrc = mplane + (size_t)(r0 - 5) * WW + cw + l16 * 4;
    const float* hsrc = hplane + (size_t)(r0 - 5) * WW + hcol;

    // ---- row fill (sequential): 16B cp.async; zeros for out-of-image rows ----
    auto fill_row = [&]() {
        float* bx = sbuf[fs][0];
        float* by = sbuf[fs][1];
        float* mdst = ((t < 16) ? bx : by) + 8 + l16 * 4;
        float* hdst = (hf ? by : bx) + hdoff;
        if ((unsigned)fr < (unsigned)HH) {
            unsigned d = (unsigned)__cvta_generic_to_shared(mdst);
            asm volatile("cp.async.cg.shared.global [%0], [%1], 16;" :: "r"(d), "l"(msrc) : "memory");
            if (hv) {
                unsigned dh = (unsigned)__cvta_generic_to_shared(hdst);
                asm volatile("cp.async.cg.shared.global [%0], [%1], 16;" :: "r"(dh), "l"(hsrc) : "memory");
            }
        } else {
            float4 z = make_float4(0.f, 0.f, 0.f, 0.f);
            *(float4*)mdst = z;
            if (hv) *(float4*)hdst = z;
        }
        ++fr;
        if (++fs == DEPTH) fs = 0;
        msrc += WW;
        hsrc += WW;
    };

    // prologue: prefetch rows 0..DIST-1, one commit group each
    #pragma unroll
    for (int p = 0; p < DIST; ++p) {
        fill_row();
        asm volatile("cp.async.commit_group;" ::: "memory");
    }

    // register ring: 11 rows x 4 packed fields (mu_x, mu_y, x^2+y^2, x*y)
    u64 RX[11], RY[11], RS[11], RP[11];
    float acc = 0.f;

    for (int blk = 0; blk < 7; ++blk) {
        #pragma unroll
        for (int ph = 0; ph < 11; ++ph) {
            const int pr = blk * 11 + ph;
            if (pr < NSTEP) {
                // warp-private pipeline: slot (pr+6)&7 = (pr-2)&7 was consumed
                // by this warp two iterations ago -> no block barrier needed.
                if (pr + DIST < NSTEP) fill_row();
                asm volatile("cp.async.commit_group;" ::: "memory");
                asm volatile("cp.async.wait_group %0;" :: "n"(DIST) : "memory");
                __syncwarp();   // make warp-mates' staged row visible

                // stage 7 aligned u64 pairs per field: XA[i] = (xr[2i], xr[2i+1])
                const u64* xv = (const u64*)sbuf[pr & 7][0] + (t + 1);
                const u64* yv = (const u64*)sbuf[pr & 7][1] + (t + 1);
                u64 XA[7], YA[7];
                #pragma unroll
                for (int i = 0; i < 7; ++i) { XA[i] = xv[i]; YA[i] = yv[i]; }
                // scalar views (register aliases, no instructions)
                float xl[7], xh[7], yl[7], yh[7];
                #pragma unroll
                for (int i = 0; i < 7; ++i) {
                    upk2(XA[i], xl[i], xh[i]);
                    upk2(YA[i], yl[i], yh[i]);
                }

                // horizontal 11-tap conv over column pair (cw+2t, cw+2t+1):
                // tap j operand = (xr[1+j], xr[2+j]);
                //  odd  j=2m+1 -> aligned  XA[m+1]          (direct, no MOV)
                //  even j=2m   -> unaligned (xh[m], xl[m+1]) (pk2)
                u64 hx = 0, hy = 0, hsum = 0, hp = 0;
                #pragma unroll
                for (int m = 0; m < 6; ++m) {          // even taps j = 2m
                    u64 ax = pk2(xh[m], xl[m + 1]);
                    u64 ay = pk2(yh[m], yl[m + 1]);
                    hx = f2fma(g2[2 * m], ax, hx);
                    hy = f2fma(g2[2 * m], ay, hy);
                    u64 ss = f2mul(ax, ax);
                    ss = f2fma(ay, ay, ss);
                    hsum = f2fma(g2[2 * m], ss, hsum);
                    hp = f2fma(g2[2 * m], f2mul(ax, ay), hp);
                }
                #pragma unroll
                for (int m = 0; m < 5; ++m) {          // odd taps j = 2m+1
                    u64 ax = XA[m + 1];
                    u64 ay = YA[m + 1];
                    hx = f2fma(g2[2 * m + 1], ax, hx);
                    hy = f2fma(g2[2 * m + 1], ay, hy);
                    u64 ss = f2mul(ax, ax);
                    ss = f2fma(ay, ay, ss);
                    hsum = f2fma(g2[2 * m + 1], ss, hsum);
                    hp = f2fma(g2[2 * m + 1], f2mul(ax, ay), hp);
                }
                RX[ph] = hx; RY[ph] = hy; RS[ph] = hsum; RP[ph] = hp;

                // vertical 11-tap conv + SSIM once ring is warm
                if (pr >= 10) {
                    u64 mx = f2mul(g2[0], RX[(ph + 1) % 11]);
                    u64 my = f2mul(g2[0], RY[(ph + 1) % 11]);
                    u64 sp = f2mul(g2[0], RS[(ph + 1) % 11]);
                    u64 sx = f2mul(g2[0], RP[(ph + 1) % 11]);
                    #pragma unroll
                    for (int k = 1; k < 11; ++k) {
                        const int sl = (ph + 1 + k) % 11;
                        mx = f2fma(g2[k], RX[sl], mx);
                        my = f2fma(g2[k], RY[sl], my);
                        sp = f2fma(g2[k], RS[sl], sp);
                        sx = f2fma(g2[k], RP[sl], sx);
                    }
                    u64 mx2 = f2mul(mx, mx);
                    u64 my2 = f2mul(my, my);
                    u64 mxy = f2mul(mx, my);
                    u64 msq = f2add(mx2, my2);
                    u64 vp  = f2fma(msq, NEG1, sp);    // sigma_x^2 + sigma_y^2
                    u64 vxy = f2fma(mxy, NEG1, sx);    // sigma_xy
                    u64 t1  = f2add(mxy, HC1);
                    u64 t2  = f2add(vxy, HC2);
                    u64 num = f2mul(t1, t2);           // ssim = 4*num/den
                    u64 t3  = f2add(msq, FC1);
                    u64 t4  = f2add(vp,  FC2);
                    u64 den = f2mul(t3, t4);
                    float n0, n1, d0, d1;
                    upk2(num, n0, n1);
                    upk2(den, d0, d1);
                    // one division for both lanes: (n0*d1 + n1*d0)/(d0*d1)
                    acc += __fdividef(fmaf(n0, d1, n1 * d0), d0 * d1);
                }
            }
        }
    }

    // ---- deterministic warp reduction -> partial ----
    #pragma unroll
    for (int o = 16; o; o >>= 1) acc += __shfl_down_sync(0xFFFFFFFFu, acc, o);

    int last = 0;
    if (t == 0) {
        g_partials[blockIdx.y * (NROWT * NSTRIP) + blockIdx.x] = acc;
        __threadfence();
        unsigned old = atomicAdd(&g_ticket, 1u);
        last = (old == NPART - 1);
    }
    last = __shfl_sync(0xFFFFFFFFu, last, 0);

    // ---- last warp: fixed-order final reduction (deterministic) ----
    if (last) {
        __threadfence();
        float v = 0.f;
        #pragma unroll
        for (int k = 0; k < NPART / 32; ++k)
            v += g_partials[t + 32 * k];
        #pragma unroll
        for (int o = 16; o; o >>= 1) v += __shfl_down_sync(0xFFFFFFFFu, v, o);
        if (t == 0) {
            // accumulated terms were num/4 / den -> scale by 4 / (B*H*W)
            out[0] = v * (4.0f / 16777216.0f);
            g_ticket = 0;   // reset for next graph replay
        }
    }
}

extern "C" void kernel_launch(void* const* d_in, const int* in_sizes, int n_in,
                              void* d_out, int out_size)
{
    const float* x   = (const float*)d_in[0];
    const float* y   = (const float*)d_in[1];
    const float* win = (const float*)d_in[2];
    float* out = (float*)d_out;

    dim3 grid(NROWT * NSTRIP, BATCH);   // (64, 64) = 4096 one-warp CTAs
    ssim_map_kernel<<<grid, 32>>>(x, y, win, out);
}